// round 1
// baseline (speedup 1.0000x reference)
#include <cuda_runtime.h>

#define N_NODES 50000
#define CDIM 128
#define XDIM 384

// Scratch (no allocations allowed) — ~77MB of __device__ globals.
__device__ float g_h0[N_NODES * CDIM];
__device__ float g_agg[N_NODES * CDIM];
__device__ float g_h1[N_NODES * CDIM];
__device__ float g_deg[N_NODES];

// ---------------------------------------------------------------------------
// zero kernel (float4 vectorized; n must be divisible by 4)
// ---------------------------------------------------------------------------
__global__ void zero_kernel(float4* __restrict__ p, int n4) {
    int i = blockIdx.x * blockDim.x + threadIdx.x;
    int stride = gridDim.x * blockDim.x;
    float4 z = make_float4(0.f, 0.f, 0.f, 0.f);
    for (; i < n4; i += stride) p[i] = z;
}

// ---------------------------------------------------------------------------
// degree: deg[dst[e]] += 1
// ---------------------------------------------------------------------------
__global__ void deg_kernel(const int* __restrict__ dst, float* __restrict__ deg, int E) {
    int i = blockIdx.x * blockDim.x + threadIdx.x;
    int stride = gridDim.x * blockDim.x;
    for (; i < E; i += stride) atomicAdd(&deg[dst[i]], 1.0f);
}

// ---------------------------------------------------------------------------
// scatter-add: agg[dst[e]][:] += h[src[e]][:]   (one warp per edge, float4/lane)
// ---------------------------------------------------------------------------
__global__ void scatter_kernel(const float* __restrict__ h,
                               const int* __restrict__ src,
                               const int* __restrict__ dst,
                               float* __restrict__ agg, int E) {
    int gtid = blockIdx.x * blockDim.x + threadIdx.x;
    int warp = gtid >> 5;
    int lane = threadIdx.x & 31;
    int nwarps = (gridDim.x * blockDim.x) >> 5;
    for (int e = warp; e < E; e += nwarps) {
        int s = src[e];
        int d = dst[e];
        const float4* hrow = (const float4*)(h + (size_t)s * CDIM);
        float4 v = hrow[lane];
        float* p = agg + (size_t)d * CDIM + lane * 4;
        atomicAdd(p + 0, v.x);
        atomicAdd(p + 1, v.y);
        atomicAdd(p + 2, v.z);
        atomicAdd(p + 3, v.w);
    }
}

// ---------------------------------------------------------------------------
// lin: out[M,128] = A[M,384] @ W[384,128] + bias
// Block: 128 threads; tile 16 rows x 128 cols; thread = 4 rows x 4 cols.
// ---------------------------------------------------------------------------
__global__ void lin_kernel(const float* __restrict__ A,
                           const float* __restrict__ W,
                           const float* __restrict__ bias,
                           float* __restrict__ out, int M) {
    __shared__ float sA[16][33];
    __shared__ float sW[32][128];

    int tid = threadIdx.x;
    int cg = tid & 31;   // column group: cols 4*cg..4*cg+3
    int rg = tid >> 5;   // row group: rows rg*4..rg*4+3 in tile
    int row0 = blockIdx.x * 16;

    float acc[4][4];
#pragma unroll
    for (int i = 0; i < 4; i++)
#pragma unroll
        for (int j = 0; j < 4; j++) acc[i][j] = 0.f;

    for (int k0 = 0; k0 < XDIM; k0 += 32) {
#pragma unroll
        for (int i = tid; i < 16 * 32; i += 128) {
            int r = i >> 5, kk = i & 31;
            int row = row0 + r;
            sA[r][kk] = (row < M) ? A[(size_t)row * XDIM + k0 + kk] : 0.f;
        }
#pragma unroll
        for (int i = tid; i < 32 * 128; i += 128) {
            int kk = i >> 7, c = i & 127;
            sW[kk][c] = W[(size_t)(k0 + kk) * CDIM + c];
        }
        __syncthreads();
#pragma unroll
        for (int kk = 0; kk < 32; kk++) {
            float4 w = *(const float4*)&sW[kk][cg * 4];
#pragma unroll
            for (int i = 0; i < 4; i++) {
                float a = sA[rg * 4 + i][kk];
                acc[i][0] += a * w.x;
                acc[i][1] += a * w.y;
                acc[i][2] += a * w.z;
                acc[i][3] += a * w.w;
            }
        }
        __syncthreads();
    }

    float4 b4 = *(const float4*)&bias[cg * 4];
#pragma unroll
    for (int i = 0; i < 4; i++) {
        int row = row0 + rg * 4 + i;
        if (row < M) {
            float4 o;
            o.x = acc[i][0] + b4.x;
            o.y = acc[i][1] + b4.y;
            o.z = acc[i][2] + b4.z;
            o.w = acc[i][3] + b4.w;
            *(float4*)&out[(size_t)row * CDIM + cg * 4] = o;
        }
    }
}

// ---------------------------------------------------------------------------
// sage combine: out = maybe_relu( (agg/max(deg,1)) @ Wl + h @ Wr + b )
// Same tiling as lin, K=128, two A streams / two W matrices fused.
// ---------------------------------------------------------------------------
__global__ void sage_combine_kernel(const float* __restrict__ agg,
                                    const float* __restrict__ deg,
                                    const float* __restrict__ h,
                                    const float* __restrict__ Wl,
                                    const float* __restrict__ Wr,
                                    const float* __restrict__ bias,
                                    float* __restrict__ out, int M, int do_relu) {
    __shared__ float sAm[16][33];
    __shared__ float sAh[16][33];
    __shared__ float sWl[32][128];
    __shared__ float sWr[32][128];
    __shared__ float sInv[16];

    int tid = threadIdx.x;
    int cg = tid & 31;
    int rg = tid >> 5;
    int row0 = blockIdx.x * 16;

    if (tid < 16) {
        int row = row0 + tid;
        float d = (row < M) ? deg[row] : 1.f;
        sInv[tid] = 1.0f / fmaxf(d, 1.0f);
    }
    __syncthreads();

    float acc[4][4];
#pragma unroll
    for (int i = 0; i < 4; i++)
#pragma unroll
        for (int j = 0; j < 4; j++) acc[i][j] = 0.f;

    for (int k0 = 0; k0 < CDIM; k0 += 32) {
#pragma unroll
        for (int i = tid; i < 16 * 32; i += 128) {
            int r = i >> 5, kk = i & 31;
            int row = row0 + r;
            if (row < M) {
                size_t off = (size_t)row * CDIM + k0 + kk;
                sAm[r][kk] = agg[off] * sInv[r];
                sAh[r][kk] = h[off];
            } else {
                sAm[r][kk] = 0.f;
                sAh[r][kk] = 0.f;
            }
        }
#pragma unroll
        for (int i = tid; i < 32 * 128; i += 128) {
            int kk = i >> 7, c = i & 127;
            size_t off = (size_t)(k0 + kk) * CDIM + c;
            sWl[kk][c] = Wl[off];
            sWr[kk][c] = Wr[off];
        }
        __syncthreads();
#pragma unroll
        for (int kk = 0; kk < 32; kk++) {
            float4 wl = *(const float4*)&sWl[kk][cg * 4];
            float4 wr = *(const float4*)&sWr[kk][cg * 4];
#pragma unroll
            for (int i = 0; i < 4; i++) {
                float am = sAm[rg * 4 + i][kk];
                float ah = sAh[rg * 4 + i][kk];
                acc[i][0] += am * wl.x + ah * wr.x;
                acc[i][1] += am * wl.y + ah * wr.y;
                acc[i][2] += am * wl.z + ah * wr.z;
                acc[i][3] += am * wl.w + ah * wr.w;
            }
        }
        __syncthreads();
    }

    float4 b4 = *(const float4*)&bias[cg * 4];
#pragma unroll
    for (int i = 0; i < 4; i++) {
        int row = row0 + rg * 4 + i;
        if (row < M) {
            float4 o;
            o.x = acc[i][0] + b4.x;
            o.y = acc[i][1] + b4.y;
            o.z = acc[i][2] + b4.z;
            o.w = acc[i][3] + b4.w;
            if (do_relu) {
                o.x = fmaxf(o.x, 0.f);
                o.y = fmaxf(o.y, 0.f);
                o.z = fmaxf(o.z, 0.f);
                o.w = fmaxf(o.w, 0.f);
            }
            *(float4*)&out[(size_t)row * CDIM + cg * 4] = o;
        }
    }
}

// ---------------------------------------------------------------------------
// classifier: out[e] = dot(h[head[e]], h[tail[e]])   (one warp per edge)
// ---------------------------------------------------------------------------
__global__ void classify_kernel(const float* __restrict__ h,
                                const int* __restrict__ head,
                                const int* __restrict__ tail,
                                float* __restrict__ out, int EL) {
    int gtid = blockIdx.x * blockDim.x + threadIdx.x;
    int warp = gtid >> 5;
    int lane = threadIdx.x & 31;
    int nwarps = (gridDim.x * blockDim.x) >> 5;
    for (int e = warp; e < EL; e += nwarps) {
        int a = head[e];
        int b = tail[e];
        const float4* ra = (const float4*)(h + (size_t)a * CDIM);
        const float4* rb = (const float4*)(h + (size_t)b * CDIM);
        float4 va = ra[lane];
        float4 vb = rb[lane];
        float s = va.x * vb.x + va.y * vb.y + va.z * vb.z + va.w * vb.w;
#pragma unroll
        for (int o = 16; o; o >>= 1) s += __shfl_xor_sync(0xffffffffu, s, o);
        if (lane == 0) out[e] = s;
    }
}

// ---------------------------------------------------------------------------
// launch
// ---------------------------------------------------------------------------
extern "C" void kernel_launch(void* const* d_in, const int* in_sizes, int n_in,
                              void* d_out, int out_size) {
    const float* x      = (const float*)d_in[0];
    const int*   ei     = (const int*)d_in[1];
    const int*   eli    = (const int*)d_in[2];
    const float* W_lin  = (const float*)d_in[3];
    const float* b_lin  = (const float*)d_in[4];
    const float* W1l    = (const float*)d_in[5];
    const float* b1     = (const float*)d_in[6];
    const float* W1r    = (const float*)d_in[7];
    const float* W2l    = (const float*)d_in[8];
    const float* b2     = (const float*)d_in[9];
    const float* W2r    = (const float*)d_in[10];
    float* out = (float*)d_out;

    int E  = in_sizes[1] / 2;
    int EL = in_sizes[2] / 2;
    const int* src = ei;
    const int* dst = ei + E;
    const int* head = eli;
    const int* tail = eli + EL;

    float *h0, *agg, *h1, *deg;
    cudaGetSymbolAddress((void**)&h0, g_h0);
    cudaGetSymbolAddress((void**)&agg, g_agg);
    cudaGetSymbolAddress((void**)&h1, g_h1);
    cudaGetSymbolAddress((void**)&deg, g_deg);

    const int M = N_NODES;
    const int ntiles = (M + 15) / 16;  // 3125

    // h0 = x @ W_lin + b_lin
    lin_kernel<<<ntiles, 128>>>(x, W_lin, b_lin, h0, M);

    // degree (shared by both layers)
    zero_kernel<<<256, 256>>>((float4*)deg, M / 4);
    deg_kernel<<<1024, 256>>>(dst, deg, E);

    // ---- layer 1 ----
    zero_kernel<<<2048, 256>>>((float4*)agg, M * CDIM / 4);
    scatter_kernel<<<2048, 256>>>(h0, src, dst, agg, E);
    sage_combine_kernel<<<ntiles, 128>>>(agg, deg, h0, W1l, W1r, b1, h1, M, 1);

    // ---- layer 2 ----
    zero_kernel<<<2048, 256>>>((float4*)agg, M * CDIM / 4);
    scatter_kernel<<<2048, 256>>>(h1, src, dst, agg, E);
    sage_combine_kernel<<<ntiles, 128>>>(agg, deg, h1, W2l, W2r, b2, h0, M, 0);

    // ---- classifier ----
    classify_kernel<<<4096, 256>>>(h0, head, tail, out, EL);
}

// round 2
// speedup vs baseline: 1.5142x; 1.5142x over previous
#include <cuda_runtime.h>

#define N_NODES 50000
#define CDIM 128
#define XDIM 384
#define E_MAX 1000000

// Scratch (__device__ globals; no allocation allowed)
__device__ float g_h0[N_NODES * CDIM];
__device__ float g_agg[N_NODES * CDIM];
__device__ float g_h1[N_NODES * CDIM];
__device__ int   g_cnt[N_NODES];
__device__ int   g_rowptr[N_NODES + 1];
__device__ int   g_cursor[N_NODES];
__device__ int   g_esrc[E_MAX];

// ---------------------------------------------------------------------------
// histogram: cnt[dst[e]]++
// ---------------------------------------------------------------------------
__global__ void hist_kernel(const int* __restrict__ dst, int* __restrict__ cnt, int E) {
    int i = blockIdx.x * blockDim.x + threadIdx.x;
    int stride = gridDim.x * blockDim.x;
    for (; i < E; i += stride) atomicAdd(&cnt[dst[i]], 1);
}

// ---------------------------------------------------------------------------
// exclusive scan of cnt -> rowptr (+ copy to cursor). Single block, 1024 thr.
// ---------------------------------------------------------------------------
__global__ void scan_kernel(const int* __restrict__ cnt, int* __restrict__ rowptr,
                            int* __restrict__ cursor, int n) {
    __shared__ int wsum[32];
    __shared__ int carry;
    int tid = threadIdx.x, lane = tid & 31, wid = tid >> 5;
    if (tid == 0) carry = 0;
    __syncthreads();
    for (int base = 0; base < n; base += 1024) {
        int idx = base + tid;
        int v = (idx < n) ? cnt[idx] : 0;
        int x = v;
#pragma unroll
        for (int off = 1; off < 32; off <<= 1) {
            int t = __shfl_up_sync(0xffffffffu, x, off);
            if (lane >= off) x += t;
        }
        if (lane == 31) wsum[wid] = x;
        __syncthreads();
        if (wid == 0) {
            int w = wsum[lane];
#pragma unroll
            for (int off = 1; off < 32; off <<= 1) {
                int t = __shfl_up_sync(0xffffffffu, w, off);
                if (lane >= off) w += t;
            }
            wsum[lane] = w;
        }
        __syncthreads();
        int incl = x + (wid ? wsum[wid - 1] : 0);
        int excl = incl - v + carry;
        if (idx < n) { rowptr[idx] = excl; cursor[idx] = excl; }
        int chunk_total = wsum[31];
        __syncthreads();
        if (tid == 0) carry += chunk_total;
        __syncthreads();
    }
    if (tid == 0) rowptr[n] = carry;
}

// ---------------------------------------------------------------------------
// fill CSR: esrc sorted by dst
// ---------------------------------------------------------------------------
__global__ void fill_kernel(const int* __restrict__ src, const int* __restrict__ dst,
                            int* __restrict__ cursor, int* __restrict__ esrc, int E) {
    int i = blockIdx.x * blockDim.x + threadIdx.x;
    int stride = gridDim.x * blockDim.x;
    for (; i < E; i += stride) {
        int d = dst[i];
        int pos = atomicAdd(&cursor[d], 1);
        esrc[pos] = src[i];
    }
}

// ---------------------------------------------------------------------------
// aggregate (mean of in-neighbors): one warp per node, float4 per lane
// ---------------------------------------------------------------------------
__global__ void aggregate_kernel(const float* __restrict__ h,
                                 const int* __restrict__ rowptr,
                                 const int* __restrict__ esrc,
                                 float* __restrict__ agg, int M) {
    int warp = (blockIdx.x * blockDim.x + threadIdx.x) >> 5;
    int lane = threadIdx.x & 31;
    if (warp >= M) return;
    int beg = rowptr[warp];
    int end = rowptr[warp + 1];
    float4 a0 = make_float4(0.f, 0.f, 0.f, 0.f);
    float4 a1 = make_float4(0.f, 0.f, 0.f, 0.f);
    int i = beg;
    for (; i + 1 < end; i += 2) {
        int s0 = esrc[i];
        int s1 = esrc[i + 1];
        float4 v0 = ((const float4*)(h + (size_t)s0 * CDIM))[lane];
        float4 v1 = ((const float4*)(h + (size_t)s1 * CDIM))[lane];
        a0.x += v0.x; a0.y += v0.y; a0.z += v0.z; a0.w += v0.w;
        a1.x += v1.x; a1.y += v1.y; a1.z += v1.z; a1.w += v1.w;
    }
    if (i < end) {
        int s0 = esrc[i];
        float4 v0 = ((const float4*)(h + (size_t)s0 * CDIM))[lane];
        a0.x += v0.x; a0.y += v0.y; a0.z += v0.z; a0.w += v0.w;
    }
    float inv = 1.0f / fmaxf((float)(end - beg), 1.0f);
    float4 r;
    r.x = (a0.x + a1.x) * inv;
    r.y = (a0.y + a1.y) * inv;
    r.z = (a0.z + a1.z) * inv;
    r.w = (a0.w + a1.w) * inv;
    ((float4*)(agg + (size_t)warp * CDIM))[lane] = r;
}

// ---------------------------------------------------------------------------
// lin: out[M,128] = A[M,384] @ W + bias.
// 256 threads, 64-row x 128-col tile, thread = 4 rows x 8 cols.
// ---------------------------------------------------------------------------
__global__ void lin_kernel(const float* __restrict__ A,
                           const float* __restrict__ W,
                           const float* __restrict__ bias,
                           float* __restrict__ out, int M) {
    __shared__ float sA[64][32];
    __shared__ float sW[32][128];

    int tid = threadIdx.x;
    int cg = tid & 15;   // cols cg*8 .. cg*8+7
    int rg = tid >> 4;   // rows rg*4 .. rg*4+3
    int row0 = blockIdx.x * 64;

    float acc[4][8];
#pragma unroll
    for (int i = 0; i < 4; i++)
#pragma unroll
        for (int j = 0; j < 8; j++) acc[i][j] = 0.f;

    for (int k0 = 0; k0 < XDIM; k0 += 32) {
#pragma unroll
        for (int i = tid; i < 64 * 32; i += 256) {
            int r = i >> 5, kk = i & 31;
            int row = row0 + r;
            sA[r][kk] = (row < M) ? A[(size_t)row * XDIM + k0 + kk] : 0.f;
        }
#pragma unroll
        for (int i = tid; i < 32 * 128; i += 256) {
            int kk = i >> 7, c = i & 127;
            sW[kk][c] = W[(size_t)(k0 + kk) * CDIM + c];
        }
        __syncthreads();
#pragma unroll
        for (int kk = 0; kk < 32; kk++) {
            float4 w0 = *(const float4*)&sW[kk][cg * 8];
            float4 w1 = *(const float4*)&sW[kk][cg * 8 + 4];
            float a[4];
#pragma unroll
            for (int i = 0; i < 4; i++) a[i] = sA[rg * 4 + i][kk];
#pragma unroll
            for (int i = 0; i < 4; i++) {
                acc[i][0] += a[i] * w0.x;
                acc[i][1] += a[i] * w0.y;
                acc[i][2] += a[i] * w0.z;
                acc[i][3] += a[i] * w0.w;
                acc[i][4] += a[i] * w1.x;
                acc[i][5] += a[i] * w1.y;
                acc[i][6] += a[i] * w1.z;
                acc[i][7] += a[i] * w1.w;
            }
        }
        __syncthreads();
    }

    float4 b0 = *(const float4*)&bias[cg * 8];
    float4 b1 = *(const float4*)&bias[cg * 8 + 4];
#pragma unroll
    for (int i = 0; i < 4; i++) {
        int row = row0 + rg * 4 + i;
        if (row < M) {
            float4 o0, o1;
            o0.x = acc[i][0] + b0.x; o0.y = acc[i][1] + b0.y;
            o0.z = acc[i][2] + b0.z; o0.w = acc[i][3] + b0.w;
            o1.x = acc[i][4] + b1.x; o1.y = acc[i][5] + b1.y;
            o1.z = acc[i][6] + b1.z; o1.w = acc[i][7] + b1.w;
            *(float4*)&out[(size_t)row * CDIM + cg * 8] = o0;
            *(float4*)&out[(size_t)row * CDIM + cg * 8 + 4] = o1;
        }
    }
}

// ---------------------------------------------------------------------------
// sage combine: out = maybe_relu( mean @ Wl + h @ Wr + b )
// mean already computed by aggregate_kernel. Same tiling as lin, K=128.
// ---------------------------------------------------------------------------
__global__ void sage_combine_kernel(const float* __restrict__ mean,
                                    const float* __restrict__ h,
                                    const float* __restrict__ Wl,
                                    const float* __restrict__ Wr,
                                    const float* __restrict__ bias,
                                    float* __restrict__ out, int M, int do_relu) {
    __shared__ float sAm[64][32];
    __shared__ float sAh[64][32];
    __shared__ float sWl[32][128];
    __shared__ float sWr[32][128];

    int tid = threadIdx.x;
    int cg = tid & 15;
    int rg = tid >> 4;
    int row0 = blockIdx.x * 64;

    float acc[4][8];
#pragma unroll
    for (int i = 0; i < 4; i++)
#pragma unroll
        for (int j = 0; j < 8; j++) acc[i][j] = 0.f;

    for (int k0 = 0; k0 < CDIM; k0 += 32) {
#pragma unroll
        for (int i = tid; i < 64 * 32; i += 256) {
            int r = i >> 5, kk = i & 31;
            int row = row0 + r;
            if (row < M) {
                size_t off = (size_t)row * CDIM + k0 + kk;
                sAm[r][kk] = mean[off];
                sAh[r][kk] = h[off];
            } else {
                sAm[r][kk] = 0.f;
                sAh[r][kk] = 0.f;
            }
        }
#pragma unroll
        for (int i = tid; i < 32 * 128; i += 256) {
            int kk = i >> 7, c = i & 127;
            size_t off = (size_t)(k0 + kk) * CDIM + c;
            sWl[kk][c] = Wl[off];
            sWr[kk][c] = Wr[off];
        }
        __syncthreads();
#pragma unroll
        for (int kk = 0; kk < 32; kk++) {
            float4 wl0 = *(const float4*)&sWl[kk][cg * 8];
            float4 wl1 = *(const float4*)&sWl[kk][cg * 8 + 4];
            float4 wr0 = *(const float4*)&sWr[kk][cg * 8];
            float4 wr1 = *(const float4*)&sWr[kk][cg * 8 + 4];
            float am[4], ah[4];
#pragma unroll
            for (int i = 0; i < 4; i++) {
                am[i] = sAm[rg * 4 + i][kk];
                ah[i] = sAh[rg * 4 + i][kk];
            }
#pragma unroll
            for (int i = 0; i < 4; i++) {
                acc[i][0] += am[i] * wl0.x + ah[i] * wr0.x;
                acc[i][1] += am[i] * wl0.y + ah[i] * wr0.y;
                acc[i][2] += am[i] * wl0.z + ah[i] * wr0.z;
                acc[i][3] += am[i] * wl0.w + ah[i] * wr0.w;
                acc[i][4] += am[i] * wl1.x + ah[i] * wr1.x;
                acc[i][5] += am[i] * wl1.y + ah[i] * wr1.y;
                acc[i][6] += am[i] * wl1.z + ah[i] * wr1.z;
                acc[i][7] += am[i] * wl1.w + ah[i] * wr1.w;
            }
        }
        __syncthreads();
    }

    float4 b0 = *(const float4*)&bias[cg * 8];
    float4 b1 = *(const float4*)&bias[cg * 8 + 4];
#pragma unroll
    for (int i = 0; i < 4; i++) {
        int row = row0 + rg * 4 + i;
        if (row < M) {
            float4 o0, o1;
            o0.x = acc[i][0] + b0.x; o0.y = acc[i][1] + b0.y;
            o0.z = acc[i][2] + b0.z; o0.w = acc[i][3] + b0.w;
            o1.x = acc[i][4] + b1.x; o1.y = acc[i][5] + b1.y;
            o1.z = acc[i][6] + b1.z; o1.w = acc[i][7] + b1.w;
            if (do_relu) {
                o0.x = fmaxf(o0.x, 0.f); o0.y = fmaxf(o0.y, 0.f);
                o0.z = fmaxf(o0.z, 0.f); o0.w = fmaxf(o0.w, 0.f);
                o1.x = fmaxf(o1.x, 0.f); o1.y = fmaxf(o1.y, 0.f);
                o1.z = fmaxf(o1.z, 0.f); o1.w = fmaxf(o1.w, 0.f);
            }
            *(float4*)&out[(size_t)row * CDIM + cg * 8] = o0;
            *(float4*)&out[(size_t)row * CDIM + cg * 8 + 4] = o1;
        }
    }
}

// ---------------------------------------------------------------------------
// classifier: out[e] = dot(h[head[e]], h[tail[e]])   (one warp per edge)
// ---------------------------------------------------------------------------
__global__ void classify_kernel(const float* __restrict__ h,
                                const int* __restrict__ head,
                                const int* __restrict__ tail,
                                float* __restrict__ out, int EL) {
    int gtid = blockIdx.x * blockDim.x + threadIdx.x;
    int warp = gtid >> 5;
    int lane = threadIdx.x & 31;
    int nwarps = (gridDim.x * blockDim.x) >> 5;
    for (int e = warp; e < EL; e += nwarps) {
        int a = head[e];
        int b = tail[e];
        float4 va = ((const float4*)(h + (size_t)a * CDIM))[lane];
        float4 vb = ((const float4*)(h + (size_t)b * CDIM))[lane];
        float s = va.x * vb.x + va.y * vb.y + va.z * vb.z + va.w * vb.w;
#pragma unroll
        for (int o = 16; o; o >>= 1) s += __shfl_xor_sync(0xffffffffu, s, o);
        if (lane == 0) out[e] = s;
    }
}

// ---------------------------------------------------------------------------
// launch
// ---------------------------------------------------------------------------
extern "C" void kernel_launch(void* const* d_in, const int* in_sizes, int n_in,
                              void* d_out, int out_size) {
    const float* x      = (const float*)d_in[0];
    const int*   ei     = (const int*)d_in[1];
    const int*   eli    = (const int*)d_in[2];
    const float* W_lin  = (const float*)d_in[3];
    const float* b_lin  = (const float*)d_in[4];
    const float* W1l    = (const float*)d_in[5];
    const float* b1     = (const float*)d_in[6];
    const float* W1r    = (const float*)d_in[7];
    const float* W2l    = (const float*)d_in[8];
    const float* b2     = (const float*)d_in[9];
    const float* W2r    = (const float*)d_in[10];
    float* out = (float*)d_out;

    int E  = in_sizes[1] / 2;
    int EL = in_sizes[2] / 2;
    const int* src = ei;
    const int* dst = ei + E;
    const int* head = eli;
    const int* tail = eli + EL;

    float *h0, *agg, *h1;
    int *cnt, *rowptr, *cursor, *esrc;
    cudaGetSymbolAddress((void**)&h0, g_h0);
    cudaGetSymbolAddress((void**)&agg, g_agg);
    cudaGetSymbolAddress((void**)&h1, g_h1);
    cudaGetSymbolAddress((void**)&cnt, g_cnt);
    cudaGetSymbolAddress((void**)&rowptr, g_rowptr);
    cudaGetSymbolAddress((void**)&cursor, g_cursor);
    cudaGetSymbolAddress((void**)&esrc, g_esrc);

    const int M = N_NODES;
    const int gemm_blocks = (M + 63) / 64;   // 782
    const int agg_blocks = (M * 32 + 255) / 256;  // warp per node

    // ---- CSR build (once; reused by both layers) ----
    cudaMemsetAsync(cnt, 0, M * sizeof(int));
    hist_kernel<<<1024, 256>>>(dst, cnt, E);
    scan_kernel<<<1, 1024>>>(cnt, rowptr, cursor, M);
    fill_kernel<<<1024, 256>>>(src, dst, cursor, esrc, E);

    // h0 = x @ W_lin + b_lin   (independent of CSR build; runs concurrently-ish in order)
    lin_kernel<<<gemm_blocks, 256>>>(x, W_lin, b_lin, h0, M);

    // ---- layer 1 ----
    aggregate_kernel<<<agg_blocks, 256>>>(h0, rowptr, esrc, agg, M);
    sage_combine_kernel<<<gemm_blocks, 256>>>(agg, h0, W1l, W1r, b1, h1, M, 1);

    // ---- layer 2 ----
    aggregate_kernel<<<agg_blocks, 256>>>(h1, rowptr, esrc, agg, M);
    sage_combine_kernel<<<gemm_blocks, 256>>>(agg, h1, W2l, W2r, b2, h0, M, 0);

    // ---- classifier ----
    classify_kernel<<<4096, 256>>>(h0, head, tail, out, EL);
}

// round 7
// speedup vs baseline: 2.6938x; 1.7790x over previous
#include <cuda_runtime.h>
#include <cstdint>

#define N_NODES 50000
#define CDIM 128
#define XDIM 384
#define E_MAX 1000000

// ---------------------------------------------------------------------------
// scratch (__device__ globals; no allocation allowed)
// ---------------------------------------------------------------------------
__device__ float g_h0[N_NODES * CDIM];
__device__ float g_agg[N_NODES * CDIM];
__device__ float g_h1[N_NODES * CDIM];
__device__ int   g_cnt[N_NODES];
__device__ int   g_rowptr[N_NODES + 1];
__device__ int   g_cursor[N_NODES];
__device__ int   g_esrc[E_MAX];

// tf32-split weights, SAME layout as input W ([K,128], k-major):
// [wlin(384x128) | w1l | w1r | w2l | w2r]
#define WT_OFF_LIN 0
#define WT_OFF_1L  (XDIM * CDIM)
#define WT_OFF_1R  (WT_OFF_1L + CDIM * CDIM)
#define WT_OFF_2L  (WT_OFF_1R + CDIM * CDIM)
#define WT_OFF_2R  (WT_OFF_2L + CDIM * CDIM)
#define WT_TOTAL   (WT_OFF_2R + CDIM * CDIM)
__device__ float g_wt_hi[WT_TOTAL];
__device__ float g_wt_lo[WT_TOTAL];

// ---------------------------------------------------------------------------
// helpers
// ---------------------------------------------------------------------------
__device__ __forceinline__ float tf32_rna(float x) {
    uint32_t u;
    asm("cvt.rna.tf32.f32 %0, %1;" : "=r"(u) : "f"(x));
    return __uint_as_float(u);
}

__device__ __forceinline__ void mma_tf32(float* d,
                                         uint32_t a0, uint32_t a1, uint32_t a2, uint32_t a3,
                                         uint32_t b0, uint32_t b1) {
    asm volatile(
        "mma.sync.aligned.m16n8k8.row.col.f32.tf32.tf32.f32 "
        "{%0,%1,%2,%3}, {%4,%5,%6,%7}, {%8,%9}, {%0,%1,%2,%3};"
        : "+f"(d[0]), "+f"(d[1]), "+f"(d[2]), "+f"(d[3])
        : "r"(a0), "r"(a1), "r"(a2), "r"(a3), "r"(b0), "r"(b1));
}

// ---------------------------------------------------------------------------
// CSR build
// ---------------------------------------------------------------------------
__global__ void hist_kernel(const int* __restrict__ dst, int* __restrict__ cnt, int E) {
    int i = blockIdx.x * blockDim.x + threadIdx.x;
    int stride = gridDim.x * blockDim.x;
    for (; i < E; i += stride) atomicAdd(&cnt[dst[i]], 1);
}

__global__ void scan_kernel(const int* __restrict__ cnt, int* __restrict__ rowptr,
                            int* __restrict__ cursor, int n) {
    __shared__ int wsum[32];
    __shared__ int carry;
    int tid = threadIdx.x, lane = tid & 31, wid = tid >> 5;
    if (tid == 0) carry = 0;
    __syncthreads();
    for (int base = 0; base < n; base += 1024) {
        int idx = base + tid;
        int v = (idx < n) ? cnt[idx] : 0;
        int x = v;
#pragma unroll
        for (int off = 1; off < 32; off <<= 1) {
            int t = __shfl_up_sync(0xffffffffu, x, off);
            if (lane >= off) x += t;
        }
        if (lane == 31) wsum[wid] = x;
        __syncthreads();
        if (wid == 0) {
            int w = wsum[lane];
#pragma unroll
            for (int off = 1; off < 32; off <<= 1) {
                int t = __shfl_up_sync(0xffffffffu, w, off);
                if (lane >= off) w += t;
            }
            wsum[lane] = w;
        }
        __syncthreads();
        int incl = x + (wid ? wsum[wid - 1] : 0);
        int excl = incl - v + carry;
        if (idx < n) { rowptr[idx] = excl; cursor[idx] = excl; }
        int chunk_total = wsum[31];
        __syncthreads();
        if (tid == 0) carry += chunk_total;
        __syncthreads();
    }
    if (tid == 0) rowptr[n] = carry;
}

__global__ void fill_kernel(const int* __restrict__ src, const int* __restrict__ dst,
                            int* __restrict__ cursor, int* __restrict__ esrc, int E) {
    int i = blockIdx.x * blockDim.x + threadIdx.x;
    int stride = gridDim.x * blockDim.x;
    for (; i < E; i += stride) {
        int d = dst[i];
        int pos = atomicAdd(&cursor[d], 1);
        esrc[pos] = src[i];
    }
}

// ---------------------------------------------------------------------------
// aggregate (mean of in-neighbors): one warp per node
// ---------------------------------------------------------------------------
__global__ void aggregate_kernel(const float* __restrict__ h,
                                 const int* __restrict__ rowptr,
                                 const int* __restrict__ esrc,
                                 float* __restrict__ agg, int M) {
    int warp = (blockIdx.x * blockDim.x + threadIdx.x) >> 5;
    int lane = threadIdx.x & 31;
    if (warp >= M) return;
    int beg = rowptr[warp];
    int end = rowptr[warp + 1];
    float4 a0 = make_float4(0.f, 0.f, 0.f, 0.f);
    float4 a1 = make_float4(0.f, 0.f, 0.f, 0.f);
    int i = beg;
    for (; i + 1 < end; i += 2) {
        int s0 = esrc[i];
        int s1 = esrc[i + 1];
        float4 v0 = ((const float4*)(h + (size_t)s0 * CDIM))[lane];
        float4 v1 = ((const float4*)(h + (size_t)s1 * CDIM))[lane];
        a0.x += v0.x; a0.y += v0.y; a0.z += v0.z; a0.w += v0.w;
        a1.x += v1.x; a1.y += v1.y; a1.z += v1.z; a1.w += v1.w;
    }
    if (i < end) {
        int s0 = esrc[i];
        float4 v0 = ((const float4*)(h + (size_t)s0 * CDIM))[lane];
        a0.x += v0.x; a0.y += v0.y; a0.z += v0.z; a0.w += v0.w;
    }
    float inv = 1.0f / fmaxf((float)(end - beg), 1.0f);
    float4 r;
    r.x = (a0.x + a1.x) * inv;
    r.y = (a0.y + a1.y) * inv;
    r.z = (a0.z + a1.z) * inv;
    r.w = (a0.w + a1.w) * inv;
    ((float4*)(agg + (size_t)warp * CDIM))[lane] = r;
}

// ---------------------------------------------------------------------------
// weight split (no transpose): W[K,128] -> hi/lo same layout
// ---------------------------------------------------------------------------
__global__ void wsplit_kernel(const float* __restrict__ W, float* __restrict__ Th,
                              float* __restrict__ Tl, int total) {
    int idx = blockIdx.x * blockDim.x + threadIdx.x;
    if (idx >= total) return;
    float w = W[idx];
    float h = tf32_rna(w);
    float l = tf32_rna(w - h);
    Th[idx] = h;
    Tl[idx] = l;
}

// ---------------------------------------------------------------------------
// 3xTF32 mma.sync GEMM:
//   out[M,128] = A1[M,K1] @ B1[K1,128] + A2[M,K2] @ B2[K2,128] + bias  (opt relu)
// B given pre-split hi/lo in original [K,128] layout.
// Block: 128x128 tile, 256 thr (8 warps: warp_m = w&3 [32 rows], warp_n = w>>2 [64 cols]).
// K staged in 32-chunks. A split to tf32 hi/lo at staging time.
// smem: sAh/sAl [128][36], sBh/sBl [32][136]  (bank-conflict-free frag loads)
// ---------------------------------------------------------------------------
#define SA_PAD 36
#define SB_PAD 136
#define SA_ELEMS (128 * SA_PAD)            // 4608
#define SB_ELEMS (32 * SB_PAD)             // 4352
#define GEMM_SMEM ((2 * SA_ELEMS + 2 * SB_ELEMS) * 4)  // 71680 B

__global__ __launch_bounds__(256, 2)
void gemm3t_kernel(const float* __restrict__ A1, int K1,
                   const float* __restrict__ A2, int K2,
                   const float* __restrict__ B1h, const float* __restrict__ B1l,
                   const float* __restrict__ B2h, const float* __restrict__ B2l,
                   const float* __restrict__ bias,
                   float* __restrict__ out, int M, int do_relu) {
    extern __shared__ float smf[];
    float* sAh = smf;
    float* sAl = smf + SA_ELEMS;
    float* sBh = smf + 2 * SA_ELEMS;
    float* sBl = smf + 2 * SA_ELEMS + SB_ELEMS;

    int tid = threadIdx.x;
    int wid = tid >> 5;
    int lane = tid & 31;
    int gi = lane >> 2;     // group id 0..7
    int tg = lane & 3;      // thread-in-group 0..3
    int wm = wid & 3;       // warp m-tile: rows wm*32..wm*32+31
    int wn = wid >> 2;      // warp n-tile: cols wn*64..wn*64+63
    int row0 = blockIdx.x * 128;

    float acc[2][8][4];
#pragma unroll
    for (int mt = 0; mt < 2; mt++)
#pragma unroll
        for (int nt = 0; nt < 8; nt++)
#pragma unroll
            for (int r = 0; r < 4; r++) acc[mt][nt][r] = 0.f;

    int nChunks = (K1 + K2) >> 5;
    int trow = tid >> 1;    // staging row 0..127
    int arow = row0 + trow;

    for (int c = 0; c < nChunks; c++) {
        int gk = c << 5;
        const float* Asrc; int lda; int kb;
        const float* Bh; const float* Bl;
        if (gk < K1) { Asrc = A1; lda = K1; kb = gk;      Bh = B1h; Bl = B1l; }
        else         { Asrc = A2; lda = K2; kb = gk - K1; Bh = B2h; Bl = B2l; }

        // --- stage A chunk: 128x32 fp32 -> hi/lo, [m][36] padded ---
        if (arow < M) {
            const float* ap = Asrc + (size_t)arow * lda + kb;
#pragma unroll
            for (int j = 0; j < 4; j++) {
                int q = (j << 1) | (tid & 1);   // 0..7
                float4 v = *(const float4*)(ap + q * 4);
                float4 h, l;
                h.x = tf32_rna(v.x); l.x = tf32_rna(v.x - h.x);
                h.y = tf32_rna(v.y); l.y = tf32_rna(v.y - h.y);
                h.z = tf32_rna(v.z); l.z = tf32_rna(v.z - h.z);
                h.w = tf32_rna(v.w); l.w = tf32_rna(v.w - h.w);
                int off = trow * SA_PAD + q * 4;
                *(float4*)(sAh + off) = h;
                *(float4*)(sAl + off) = l;
            }
        } else {
            float4 z = make_float4(0.f, 0.f, 0.f, 0.f);
#pragma unroll
            for (int j = 0; j < 4; j++) {
                int q = (j << 1) | (tid & 1);
                int off = trow * SA_PAD + q * 4;
                *(float4*)(sAh + off) = z;
                *(float4*)(sAl + off) = z;
            }
        }
        // --- stage B chunk: 32x128 pre-split, [k][136] padded ---
#pragma unroll
        for (int t = 0; t < 4; t++) {
            int idx = tid + t * 256;            // 0..1023 float4 units
            int kk = idx >> 5;
            int c4 = idx & 31;
            size_t goff = (size_t)(kb + kk) * CDIM + c4 * 4;
            int soff = kk * SB_PAD + c4 * 4;
            *(float4*)(sBh + soff) = *(const float4*)(Bh + goff);
            *(float4*)(sBl + soff) = *(const float4*)(Bl + goff);
        }
        __syncthreads();

        // --- compute: 4 k-steps of 8 ---
#pragma unroll
        for (int ks = 0; ks < 4; ks++) {
            int k0 = ks << 3;
            uint32_t aH[2][4], aL[2][4];
#pragma unroll
            for (int mt = 0; mt < 2; mt++) {
                int m0 = (wm << 5) + (mt << 4) + gi;
                int base0 = m0 * SA_PAD + k0 + tg;
                int base1 = (m0 + 8) * SA_PAD + k0 + tg;
                aH[mt][0] = __float_as_uint(sAh[base0]);
                aH[mt][1] = __float_as_uint(sAh[base1]);
                aH[mt][2] = __float_as_uint(sAh[base0 + 4]);
                aH[mt][3] = __float_as_uint(sAh[base1 + 4]);
                aL[mt][0] = __float_as_uint(sAl[base0]);
                aL[mt][1] = __float_as_uint(sAl[base1]);
                aL[mt][2] = __float_as_uint(sAl[base0 + 4]);
                aL[mt][3] = __float_as_uint(sAl[base1 + 4]);
            }
#pragma unroll
            for (int nt = 0; nt < 8; nt++) {
                int bn = (wn << 6) + (nt << 3) + gi;
                int kb0 = (k0 + tg) * SB_PAD + bn;
                int kb1 = (k0 + tg + 4) * SB_PAD + bn;
                uint32_t bH0 = __float_as_uint(sBh[kb0]);
                uint32_t bH1 = __float_as_uint(sBh[kb1]);
                uint32_t bL0 = __float_as_uint(sBl[kb0]);
                uint32_t bL1 = __float_as_uint(sBl[kb1]);
#pragma unroll
                for (int mt = 0; mt < 2; mt++) {
                    mma_tf32(acc[mt][nt], aH[mt][0], aH[mt][1], aH[mt][2], aH[mt][3], bH0, bH1);
                    mma_tf32(acc[mt][nt], aH[mt][0], aH[mt][1], aH[mt][2], aH[mt][3], bL0, bL1);
                    mma_tf32(acc[mt][nt], aL[mt][0], aL[mt][1], aL[mt][2], aL[mt][3], bH0, bH1);
                }
            }
        }
        __syncthreads();
    }

    // --- epilogue: direct STG, bias + optional relu ---
#pragma unroll
    for (int mt = 0; mt < 2; mt++) {
        int r0 = row0 + (wm << 5) + (mt << 4) + gi;
        int r1 = r0 + 8;
#pragma unroll
        for (int nt = 0; nt < 8; nt++) {
            int cc = (wn << 6) + (nt << 3) + (tg << 1);
            float b0 = bias[cc], b1 = bias[cc + 1];
            float2 o0, o1;
            o0.x = acc[mt][nt][0] + b0; o0.y = acc[mt][nt][1] + b1;
            o1.x = acc[mt][nt][2] + b0; o1.y = acc[mt][nt][3] + b1;
            if (do_relu) {
                o0.x = fmaxf(o0.x, 0.f); o0.y = fmaxf(o0.y, 0.f);
                o1.x = fmaxf(o1.x, 0.f); o1.y = fmaxf(o1.y, 0.f);
            }
            if (r0 < M) *(float2*)&out[(size_t)r0 * CDIM + cc] = o0;
            if (r1 < M) *(float2*)&out[(size_t)r1 * CDIM + cc] = o1;
        }
    }
}

// ---------------------------------------------------------------------------
// classifier: out[e] = dot(h[head[e]], h[tail[e]])   (one warp per edge)
// ---------------------------------------------------------------------------
__global__ void classify_kernel(const float* __restrict__ h,
                                const int* __restrict__ head,
                                const int* __restrict__ tail,
                                float* __restrict__ out, int EL) {
    int gtid = blockIdx.x * blockDim.x + threadIdx.x;
    int warp = gtid >> 5;
    int lane = threadIdx.x & 31;
    int nwarps = (gridDim.x * blockDim.x) >> 5;
    for (int e = warp; e < EL; e += nwarps) {
        int a = head[e];
        int b = tail[e];
        float4 va = ((const float4*)(h + (size_t)a * CDIM))[lane];
        float4 vb = ((const float4*)(h + (size_t)b * CDIM))[lane];
        float s = va.x * vb.x + va.y * vb.y + va.z * vb.z + va.w * vb.w;
#pragma unroll
        for (int o = 16; o; o >>= 1) s += __shfl_xor_sync(0xffffffffu, s, o);
        if (lane == 0) out[e] = s;
    }
}

// ---------------------------------------------------------------------------
// launch
// ---------------------------------------------------------------------------
extern "C" void kernel_launch(void* const* d_in, const int* in_sizes, int n_in,
                              void* d_out, int out_size) {
    const float* x      = (const float*)d_in[0];
    const int*   ei     = (const int*)d_in[1];
    const int*   eli    = (const int*)d_in[2];
    const float* W_lin  = (const float*)d_in[3];
    const float* b_lin  = (const float*)d_in[4];
    const float* W1l    = (const float*)d_in[5];
    const float* b1     = (const float*)d_in[6];
    const float* W1r    = (const float*)d_in[7];
    const float* W2l    = (const float*)d_in[8];
    const float* b2     = (const float*)d_in[9];
    const float* W2r    = (const float*)d_in[10];
    float* out = (float*)d_out;

    int E  = in_sizes[1] / 2;
    int EL = in_sizes[2] / 2;
    const int* src = ei;
    const int* dst = ei + E;
    const int* head = eli;
    const int* tail = eli + EL;

    float *h0, *agg, *h1, *wth, *wtl;
    int *cnt, *rowptr, *cursor, *esrc;
    cudaGetSymbolAddress((void**)&h0, g_h0);
    cudaGetSymbolAddress((void**)&agg, g_agg);
    cudaGetSymbolAddress((void**)&h1, g_h1);
    cudaGetSymbolAddress((void**)&cnt, g_cnt);
    cudaGetSymbolAddress((void**)&rowptr, g_rowptr);
    cudaGetSymbolAddress((void**)&cursor, g_cursor);
    cudaGetSymbolAddress((void**)&esrc, g_esrc);
    cudaGetSymbolAddress((void**)&wth, g_wt_hi);
    cudaGetSymbolAddress((void**)&wtl, g_wt_lo);

    cudaFuncSetAttribute(gemm3t_kernel, cudaFuncAttributeMaxDynamicSharedMemorySize, GEMM_SMEM);

    const int M = N_NODES;
    const int gemm_blocks = (M + 127) / 128;      // 391
    const int agg_blocks = (M * 32 + 255) / 256;  // warp per node

    // ---- CSR build ----
    cudaMemsetAsync(cnt, 0, M * sizeof(int));
    hist_kernel<<<1024, 256>>>(dst, cnt, E);
    scan_kernel<<<1, 1024>>>(cnt, rowptr, cursor, M);
    fill_kernel<<<1024, 256>>>(src, dst, cursor, esrc, E);

    // ---- weight tf32 split (layout preserved) ----
    wsplit_kernel<<<(XDIM * CDIM + 255) / 256, 256>>>(W_lin, wth + WT_OFF_LIN, wtl + WT_OFF_LIN, XDIM * CDIM);
    wsplit_kernel<<<(CDIM * CDIM + 255) / 256, 256>>>(W1l, wth + WT_OFF_1L, wtl + WT_OFF_1L, CDIM * CDIM);
    wsplit_kernel<<<(CDIM * CDIM + 255) / 256, 256>>>(W1r, wth + WT_OFF_1R, wtl + WT_OFF_1R, CDIM * CDIM);
    wsplit_kernel<<<(CDIM * CDIM + 255) / 256, 256>>>(W2l, wth + WT_OFF_2L, wtl + WT_OFF_2L, CDIM * CDIM);
    wsplit_kernel<<<(CDIM * CDIM + 255) / 256, 256>>>(W2r, wth + WT_OFF_2R, wtl + WT_OFF_2R, CDIM * CDIM);

    // ---- h0 = x @ W_lin + b_lin ----
    gemm3t_kernel<<<gemm_blocks, 256, GEMM_SMEM>>>(
        x, XDIM, (const float*)nullptr, 0,
        wth + WT_OFF_LIN, wtl + WT_OFF_LIN, (const float*)nullptr, (const float*)nullptr,
        b_lin, h0, M, 0);

    // ---- layer 1: h1 = relu(mean@W1l + h0@W1r + b1) ----
    aggregate_kernel<<<agg_blocks, 256>>>(h0, rowptr, esrc, agg, M);
    gemm3t_kernel<<<gemm_blocks, 256, GEMM_SMEM>>>(
        agg, CDIM, h0, CDIM,
        wth + WT_OFF_1L, wtl + WT_OFF_1L, wth + WT_OFF_1R, wtl + WT_OFF_1R,
        b1, h1, M, 1);

    // ---- layer 2: h2 = mean@W2l + h1@W2r + b2 (into h0 buffer) ----
    aggregate_kernel<<<agg_blocks, 256>>>(h1, rowptr, esrc, agg, M);
    gemm3t_kernel<<<gemm_blocks, 256, GEMM_SMEM>>>(
        agg, CDIM, h1, CDIM,
        wth + WT_OFF_2L, wtl + WT_OFF_2L, wth + WT_OFF_2R, wtl + WT_OFF_2R,
        b2, h0, M, 0);

    // ---- classifier ----
    classify_kernel<<<4096, 256>>>(h0, head, tail, out, EL);
}

// round 8
// speedup vs baseline: 3.0233x; 1.1223x over previous
#include <cuda_runtime.h>
#include <cstdint>

#define N_NODES 50000
#define CDIM 128
#define XDIM 384
#define E_MAX 1000000

// ---------------------------------------------------------------------------
// scratch (__device__ globals; no allocation allowed)
// ---------------------------------------------------------------------------
__device__ float g_h0[N_NODES * CDIM];
__device__ float g_agg[N_NODES * CDIM];
__device__ float g_h1[N_NODES * CDIM];
__device__ int   g_cnt[N_NODES];
__device__ int   g_rowptr[N_NODES + 1];
__device__ int   g_cursor[N_NODES];
__device__ int   g_esrc[E_MAX];

// tf32-split weights, SAME layout as input W ([K,128], k-major):
// [wlin(384x128) | w1l | w1r | w2l | w2r]
#define WT_OFF_LIN 0
#define WT_OFF_1L  (XDIM * CDIM)
#define WT_OFF_1R  (WT_OFF_1L + CDIM * CDIM)
#define WT_OFF_2L  (WT_OFF_1R + CDIM * CDIM)
#define WT_OFF_2R  (WT_OFF_2L + CDIM * CDIM)
#define WT_TOTAL   (WT_OFF_2R + CDIM * CDIM)
__device__ float g_wt_hi[WT_TOTAL];
__device__ float g_wt_lo[WT_TOTAL];

// ---------------------------------------------------------------------------
// helpers
// ---------------------------------------------------------------------------
__device__ __forceinline__ float tf32_rna(float x) {
    uint32_t u;
    asm("cvt.rna.tf32.f32 %0, %1;" : "=r"(u) : "f"(x));
    return __uint_as_float(u);
}

__device__ __forceinline__ uint32_t smem_u32(const void* p) {
    uint32_t a;
    asm("{ .reg .u64 t; cvta.to.shared.u64 t, %1; cvt.u32.u64 %0, t; }" : "=r"(a) : "l"(p));
    return a;
}

__device__ __forceinline__ void cp_async16(uint32_t smem_addr, const void* gptr) {
    asm volatile("cp.async.cg.shared.global [%0], [%1], 16;" :: "r"(smem_addr), "l"(gptr));
}
#define CP_COMMIT() asm volatile("cp.async.commit_group;" ::: "memory")
#define CP_WAIT(n)  asm volatile("cp.async.wait_group %0;" :: "n"(n) : "memory")

__device__ __forceinline__ void mma_tf32(float* d,
                                         uint32_t a0, uint32_t a1, uint32_t a2, uint32_t a3,
                                         uint32_t b0, uint32_t b1) {
    asm volatile(
        "mma.sync.aligned.m16n8k8.row.col.f32.tf32.tf32.f32 "
        "{%0,%1,%2,%3}, {%4,%5,%6,%7}, {%8,%9}, {%0,%1,%2,%3};"
        : "+f"(d[0]), "+f"(d[1]), "+f"(d[2]), "+f"(d[3])
        : "r"(a0), "r"(a1), "r"(a2), "r"(a3), "r"(b0), "r"(b1));
}

// ---------------------------------------------------------------------------
// CSR build
// ---------------------------------------------------------------------------
__global__ void hist_kernel(const int* __restrict__ dst, int* __restrict__ cnt, int E) {
    int i = blockIdx.x * blockDim.x + threadIdx.x;
    int stride = gridDim.x * blockDim.x;
    for (; i < E; i += stride) atomicAdd(&cnt[dst[i]], 1);
}

__global__ void scan_kernel(const int* __restrict__ cnt, int* __restrict__ rowptr,
                            int* __restrict__ cursor, int n) {
    __shared__ int wsum[32];
    __shared__ int carry;
    int tid = threadIdx.x, lane = tid & 31, wid = tid >> 5;
    if (tid == 0) carry = 0;
    __syncthreads();
    for (int base = 0; base < n; base += 1024) {
        int idx = base + tid;
        int v = (idx < n) ? cnt[idx] : 0;
        int x = v;
#pragma unroll
        for (int off = 1; off < 32; off <<= 1) {
            int t = __shfl_up_sync(0xffffffffu, x, off);
            if (lane >= off) x += t;
        }
        if (lane == 31) wsum[wid] = x;
        __syncthreads();
        if (wid == 0) {
            int w = wsum[lane];
#pragma unroll
            for (int off = 1; off < 32; off <<= 1) {
                int t = __shfl_up_sync(0xffffffffu, w, off);
                if (lane >= off) w += t;
            }
            wsum[lane] = w;
        }
        __syncthreads();
        int incl = x + (wid ? wsum[wid - 1] : 0);
        int excl = incl - v + carry;
        if (idx < n) { rowptr[idx] = excl; cursor[idx] = excl; }
        int chunk_total = wsum[31];
        __syncthreads();
        if (tid == 0) carry += chunk_total;
        __syncthreads();
    }
    if (tid == 0) rowptr[n] = carry;
}

__global__ void fill_kernel(const int* __restrict__ src, const int* __restrict__ dst,
                            int* __restrict__ cursor, int* __restrict__ esrc, int E) {
    int i = blockIdx.x * blockDim.x + threadIdx.x;
    int stride = gridDim.x * blockDim.x;
    for (; i < E; i += stride) {
        int d = dst[i];
        int pos = atomicAdd(&cursor[d], 1);
        esrc[pos] = src[i];
    }
}

// ---------------------------------------------------------------------------
// aggregate (mean of in-neighbors): one warp per node, 4-deep unroll for MLP
// ---------------------------------------------------------------------------
__global__ void aggregate_kernel(const float* __restrict__ h,
                                 const int* __restrict__ rowptr,
                                 const int* __restrict__ esrc,
                                 float* __restrict__ agg, int M) {
    int warp = (blockIdx.x * blockDim.x + threadIdx.x) >> 5;
    int lane = threadIdx.x & 31;
    if (warp >= M) return;
    int beg = rowptr[warp];
    int end = rowptr[warp + 1];
    float4 a0 = make_float4(0.f, 0.f, 0.f, 0.f);
    float4 a1 = make_float4(0.f, 0.f, 0.f, 0.f);
    float4 a2 = make_float4(0.f, 0.f, 0.f, 0.f);
    float4 a3 = make_float4(0.f, 0.f, 0.f, 0.f);
    int i = beg;
    for (; i + 3 < end; i += 4) {
        int s0 = esrc[i], s1 = esrc[i + 1], s2 = esrc[i + 2], s3 = esrc[i + 3];
        float4 v0 = ((const float4*)(h + (size_t)s0 * CDIM))[lane];
        float4 v1 = ((const float4*)(h + (size_t)s1 * CDIM))[lane];
        float4 v2 = ((const float4*)(h + (size_t)s2 * CDIM))[lane];
        float4 v3 = ((const float4*)(h + (size_t)s3 * CDIM))[lane];
        a0.x += v0.x; a0.y += v0.y; a0.z += v0.z; a0.w += v0.w;
        a1.x += v1.x; a1.y += v1.y; a1.z += v1.z; a1.w += v1.w;
        a2.x += v2.x; a2.y += v2.y; a2.z += v2.z; a2.w += v2.w;
        a3.x += v3.x; a3.y += v3.y; a3.z += v3.z; a3.w += v3.w;
    }
    for (; i < end; i++) {
        int s0 = esrc[i];
        float4 v0 = ((const float4*)(h + (size_t)s0 * CDIM))[lane];
        a0.x += v0.x; a0.y += v0.y; a0.z += v0.z; a0.w += v0.w;
    }
    float inv = 1.0f / fmaxf((float)(end - beg), 1.0f);
    float4 r;
    r.x = (a0.x + a1.x + a2.x + a3.x) * inv;
    r.y = (a0.y + a1.y + a2.y + a3.y) * inv;
    r.z = (a0.z + a1.z + a2.z + a3.z) * inv;
    r.w = (a0.w + a1.w + a2.w + a3.w) * inv;
    ((float4*)(agg + (size_t)warp * CDIM))[lane] = r;
}

// ---------------------------------------------------------------------------
// weight split (all 5 matrices, one launch): W[K,128] -> hi/lo same layout
// ---------------------------------------------------------------------------
__global__ void wsplit_all_kernel(const float* __restrict__ Wlin,
                                  const float* __restrict__ W1l,
                                  const float* __restrict__ W1r,
                                  const float* __restrict__ W2l,
                                  const float* __restrict__ W2r,
                                  float* __restrict__ Th, float* __restrict__ Tl) {
    int idx = blockIdx.x * blockDim.x + threadIdx.x;
    if (idx >= WT_TOTAL) return;
    float w;
    if (idx < WT_OFF_1L)      w = Wlin[idx];
    else if (idx < WT_OFF_1R) w = W1l[idx - WT_OFF_1L];
    else if (idx < WT_OFF_2L) w = W1r[idx - WT_OFF_1R];
    else if (idx < WT_OFF_2R) w = W2l[idx - WT_OFF_2L];
    else                      w = W2r[idx - WT_OFF_2R];
    float h = tf32_rna(w);
    float l = tf32_rna(w - h);
    Th[idx] = h;
    Tl[idx] = l;
}

// ---------------------------------------------------------------------------
// 3xTF32 mma.sync GEMM with cp.async double-buffered B:
//   out[M,128] = A1[M,K1] @ B1[K1,128] + A2[M,K2] @ B2[K2,128] + bias (opt relu)
// Block: 128x128 tile, 256 thr (8 warps: wm=w&3 [32 rows], wn=w>>2 [64 cols]).
// smem: sAh/sAl [128][36] single, sB[2 stages][hi|lo][32][136]
// ---------------------------------------------------------------------------
#define SA_PAD 36
#define SB_PAD 136
#define SA_ELEMS (128 * SA_PAD)            // 4608
#define SB_ELEMS (32 * SB_PAD)             // 4352
#define GEMM_SMEM ((2 * SA_ELEMS + 4 * SB_ELEMS) * 4)  // 106496 B

__global__ __launch_bounds__(256, 2)
void gemm3t_kernel(const float* __restrict__ A1, int K1,
                   const float* __restrict__ A2, int K2,
                   const float* __restrict__ B1h, const float* __restrict__ B1l,
                   const float* __restrict__ B2h, const float* __restrict__ B2l,
                   const float* __restrict__ bias,
                   float* __restrict__ out, int M, int do_relu) {
    extern __shared__ float smf[];
    float* sAh = smf;
    float* sAl = smf + SA_ELEMS;
    float* sB  = smf + 2 * SA_ELEMS;   // [stage][hi/lo][SB_ELEMS]

    int tid = threadIdx.x;
    int wid = tid >> 5;
    int lane = tid & 31;
    int gi = lane >> 2;
    int tg = lane & 3;
    int wm = wid & 3;
    int wn = wid >> 2;
    int row0 = blockIdx.x * 128;

    float acc[2][8][4];
#pragma unroll
    for (int mt = 0; mt < 2; mt++)
#pragma unroll
        for (int nt = 0; nt < 8; nt++)
#pragma unroll
            for (int r = 0; r < 4; r++) acc[mt][nt][r] = 0.f;

    int nChunks = (K1 + K2) >> 5;
    int trow = tid >> 1;
    int arow = row0 + trow;

    // B-issue helper (macro-ish lambda): stage chunk c's B into buffer buf
    auto issue_B = [&](int c, int buf) {
        int gk = c << 5;
        const float* Bh; const float* Bl; int kb;
        if (gk < K1) { Bh = B1h; Bl = B1l; kb = gk; }
        else         { Bh = B2h; Bl = B2l; kb = gk - K1; }
        float* dsth = sB + buf * 2 * SB_ELEMS;
        float* dstl = dsth + SB_ELEMS;
#pragma unroll
        for (int t = 0; t < 4; t++) {
            int idx = tid + t * 256;
            int kk = idx >> 5;
            int c4 = idx & 31;
            size_t goff = (size_t)(kb + kk) * CDIM + c4 * 4;
            int soff = kk * SB_PAD + c4 * 4;
            cp_async16(smem_u32(dsth + soff), Bh + goff);
            cp_async16(smem_u32(dstl + soff), Bl + goff);
        }
        CP_COMMIT();
    };

    issue_B(0, 0);

    for (int c = 0; c < nChunks; c++) {
        int buf = c & 1;
        int gk = c << 5;
        const float* Asrc; int lda; int kb;
        if (gk < K1) { Asrc = A1; lda = K1; kb = gk; }
        else         { Asrc = A2; lda = K2; kb = gk - K1; }

        // --- stage A chunk: 128x32 fp32 -> hi/lo, [m][36] padded ---
        if (arow < M) {
            const float* ap = Asrc + (size_t)arow * lda + kb;
#pragma unroll
            for (int j = 0; j < 4; j++) {
                int q = (j << 1) | (tid & 1);
                float4 v = *(const float4*)(ap + q * 4);
                float4 h, l;
                h.x = tf32_rna(v.x); l.x = tf32_rna(v.x - h.x);
                h.y = tf32_rna(v.y); l.y = tf32_rna(v.y - h.y);
                h.z = tf32_rna(v.z); l.z = tf32_rna(v.z - h.z);
                h.w = tf32_rna(v.w); l.w = tf32_rna(v.w - h.w);
                int off = trow * SA_PAD + q * 4;
                *(float4*)(sAh + off) = h;
                *(float4*)(sAl + off) = l;
            }
        } else {
            float4 z = make_float4(0.f, 0.f, 0.f, 0.f);
#pragma unroll
            for (int j = 0; j < 4; j++) {
                int q = (j << 1) | (tid & 1);
                int off = trow * SA_PAD + q * 4;
                *(float4*)(sAh + off) = z;
                *(float4*)(sAl + off) = z;
            }
        }

        // issue next B while this chunk computes
        if (c + 1 < nChunks) {
            issue_B(c + 1, buf ^ 1);
            CP_WAIT(1);     // chunk c's group complete; c+1 may be in flight
        } else {
            CP_WAIT(0);
        }
        __syncthreads();

        const float* sBh = sB + buf * 2 * SB_ELEMS;
        const float* sBl = sBh + SB_ELEMS;

#pragma unroll
        for (int ks = 0; ks < 4; ks++) {
            int k0 = ks << 3;
            uint32_t aH[2][4], aL[2][4];
#pragma unroll
            for (int mt = 0; mt < 2; mt++) {
                int m0 = (wm << 5) + (mt << 4) + gi;
                int base0 = m0 * SA_PAD + k0 + tg;
                int base1 = (m0 + 8) * SA_PAD + k0 + tg;
                aH[mt][0] = __float_as_uint(sAh[base0]);
                aH[mt][1] = __float_as_uint(sAh[base1]);
                aH[mt][2] = __float_as_uint(sAh[base0 + 4]);
                aH[mt][3] = __float_as_uint(sAh[base1 + 4]);
                aL[mt][0] = __float_as_uint(sAl[base0]);
                aL[mt][1] = __float_as_uint(sAl[base1]);
                aL[mt][2] = __float_as_uint(sAl[base0 + 4]);
                aL[mt][3] = __float_as_uint(sAl[base1 + 4]);
            }
#pragma unroll
            for (int nt = 0; nt < 8; nt++) {
                int bn = (wn << 6) + (nt << 3) + gi;
                int kb0 = (k0 + tg) * SB_PAD + bn;
                int kb1 = (k0 + tg + 4) * SB_PAD + bn;
                uint32_t bH0 = __float_as_uint(sBh[kb0]);
                uint32_t bH1 = __float_as_uint(sBh[kb1]);
                uint32_t bL0 = __float_as_uint(sBl[kb0]);
                uint32_t bL1 = __float_as_uint(sBl[kb1]);
#pragma unroll
                for (int mt = 0; mt < 2; mt++) {
                    mma_tf32(acc[mt][nt], aH[mt][0], aH[mt][1], aH[mt][2], aH[mt][3], bH0, bH1);
                    mma_tf32(acc[mt][nt], aH[mt][0], aH[mt][1], aH[mt][2], aH[mt][3], bL0, bL1);
                    mma_tf32(acc[mt][nt], aL[mt][0], aL[mt][1], aL[mt][2], aL[mt][3], bH0, bH1);
                }
            }
        }
        __syncthreads();
    }

    // --- epilogue: direct STG, bias + optional relu ---
#pragma unroll
    for (int mt = 0; mt < 2; mt++) {
        int r0 = row0 + (wm << 5) + (mt << 4) + gi;
        int r1 = r0 + 8;
#pragma unroll
        for (int nt = 0; nt < 8; nt++) {
            int cc = (wn << 6) + (nt << 3) + (tg << 1);
            float b0 = bias[cc], b1 = bias[cc + 1];
            float2 o0, o1;
            o0.x = acc[mt][nt][0] + b0; o0.y = acc[mt][nt][1] + b1;
            o1.x = acc[mt][nt][2] + b0; o1.y = acc[mt][nt][3] + b1;
            if (do_relu) {
                o0.x = fmaxf(o0.x, 0.f); o0.y = fmaxf(o0.y, 0.f);
                o1.x = fmaxf(o1.x, 0.f); o1.y = fmaxf(o1.y, 0.f);
            }
            if (r0 < M) *(float2*)&out[(size_t)r0 * CDIM + cc] = o0;
            if (r1 < M) *(float2*)&out[(size_t)r1 * CDIM + cc] = o1;
        }
    }
}

// ---------------------------------------------------------------------------
// classifier: out[e] = dot(h[head[e]], h[tail[e]]) — 2 edges per warp iter
// ---------------------------------------------------------------------------
__global__ void classify_kernel(const float* __restrict__ h,
                                const int* __restrict__ head,
                                const int* __restrict__ tail,
                                float* __restrict__ out, int EL) {
    int gtid = blockIdx.x * blockDim.x + threadIdx.x;
    int warp = gtid >> 5;
    int lane = threadIdx.x & 31;
    int nwarps = (gridDim.x * blockDim.x) >> 5;
    for (int e = warp * 2; e < EL; e += nwarps * 2) {
        int a0 = head[e];
        int b0 = tail[e];
        float4 va0 = ((const float4*)(h + (size_t)a0 * CDIM))[lane];
        float4 vb0 = ((const float4*)(h + (size_t)b0 * CDIM))[lane];
        bool has1 = (e + 1 < EL);
        float4 va1, vb1;
        if (has1) {
            int a1 = head[e + 1];
            int b1 = tail[e + 1];
            va1 = ((const float4*)(h + (size_t)a1 * CDIM))[lane];
            vb1 = ((const float4*)(h + (size_t)b1 * CDIM))[lane];
        }
        float s0 = va0.x * vb0.x + va0.y * vb0.y + va0.z * vb0.z + va0.w * vb0.w;
#pragma unroll
        for (int o = 16; o; o >>= 1) s0 += __shfl_xor_sync(0xffffffffu, s0, o);
        if (lane == 0) out[e] = s0;
        if (has1) {
            float s1 = va1.x * vb1.x + va1.y * vb1.y + va1.z * vb1.z + va1.w * vb1.w;
#pragma unroll
            for (int o = 16; o; o >>= 1) s1 += __shfl_xor_sync(0xffffffffu, s1, o);
            if (lane == 0) out[e + 1] = s1;
        }
    }
}

// ---------------------------------------------------------------------------
// launch
// ---------------------------------------------------------------------------
extern "C" void kernel_launch(void* const* d_in, const int* in_sizes, int n_in,
                              void* d_out, int out_size) {
    const float* x      = (const float*)d_in[0];
    const int*   ei     = (const int*)d_in[1];
    const int*   eli    = (const int*)d_in[2];
    const float* W_lin  = (const float*)d_in[3];
    const float* b_lin  = (const float*)d_in[4];
    const float* W1l    = (const float*)d_in[5];
    const float* b1     = (const float*)d_in[6];
    const float* W1r    = (const float*)d_in[7];
    const float* W2l    = (const float*)d_in[8];
    const float* b2     = (const float*)d_in[9];
    const float* W2r    = (const float*)d_in[10];
    float* out = (float*)d_out;

    int E  = in_sizes[1] / 2;
    int EL = in_sizes[2] / 2;
    const int* src = ei;
    const int* dst = ei + E;
    const int* head = eli;
    const int* tail = eli + EL;

    float *h0, *agg, *h1, *wth, *wtl;
    int *cnt, *rowptr, *cursor, *esrc;
    cudaGetSymbolAddress((void**)&h0, g_h0);
    cudaGetSymbolAddress((void**)&agg, g_agg);
    cudaGetSymbolAddress((void**)&h1, g_h1);
    cudaGetSymbolAddress((void**)&cnt, g_cnt);
    cudaGetSymbolAddress((void**)&rowptr, g_rowptr);
    cudaGetSymbolAddress((void**)&cursor, g_cursor);
    cudaGetSymbolAddress((void**)&esrc, g_esrc);
    cudaGetSymbolAddress((void**)&wth, g_wt_hi);
    cudaGetSymbolAddress((void**)&wtl, g_wt_lo);

    cudaFuncSetAttribute(gemm3t_kernel, cudaFuncAttributeMaxDynamicSharedMemorySize, GEMM_SMEM);

    const int M = N_NODES;
    const int gemm_blocks = (M + 127) / 128;      // 391
    const int agg_blocks = (M * 32 + 255) / 256;  // warp per node

    // ---- CSR build ----
    cudaMemsetAsync(cnt, 0, M * sizeof(int));
    hist_kernel<<<1024, 256>>>(dst, cnt, E);
    scan_kernel<<<1, 1024>>>(cnt, rowptr, cursor, M);
    fill_kernel<<<1024, 256>>>(src, dst, cursor, esrc, E);

    // ---- weight tf32 split (single launch) ----
    wsplit_all_kernel<<<(WT_TOTAL + 255) / 256, 256>>>(W_lin, W1l, W1r, W2l, W2r, wth, wtl);

    // ---- h0 = x @ W_lin + b_lin ----
    gemm3t_kernel<<<gemm_blocks, 256, GEMM_SMEM>>>(
        x, XDIM, (const float*)nullptr, 0,
        wth + WT_OFF_LIN, wtl + WT_OFF_LIN, (const float*)nullptr, (const float*)nullptr,
        b_lin, h0, M, 0);

    // ---- layer 1: h1 = relu(mean@W1l + h0@W1r + b1) ----
    aggregate_kernel<<<agg_blocks, 256>>>(h0, rowptr, esrc, agg, M);
    gemm3t_kernel<<<gemm_blocks, 256, GEMM_SMEM>>>(
        agg, CDIM, h0, CDIM,
        wth + WT_OFF_1L, wtl + WT_OFF_1L, wth + WT_OFF_1R, wtl + WT_OFF_1R,
        b1, h1, M, 1);

    // ---- layer 2: h2 = mean@W2l + h1@W2r + b2 (into h0 buffer) ----
    aggregate_kernel<<<agg_blocks, 256>>>(h1, rowptr, esrc, agg, M);
    gemm3t_kernel<<<gemm_blocks, 256, GEMM_SMEM>>>(
        agg, CDIM, h1, CDIM,
        wth + WT_OFF_2L, wtl + WT_OFF_2L, wth + WT_OFF_2R, wtl + WT_OFF_2R,
        b2, h0, M, 0);

    // ---- classifier ----
    classify_kernel<<<4096, 256>>>(h0, head, tail, out, EL);
}